// round 1
// baseline (speedup 1.0000x reference)
#include <cuda_runtime.h>
#include <cstdint>

// WMeasure_Rot: elementwise quantum-measurement update.
// inputs:  d_in[0]=input[B*N] f32, d_in[1]=angles[B*N] f32, d_in[2]=last_res[B*N] f32
// output:  d_out[0 : B*N)      = meas_res
//          d_out[B*N : 2*B*N)  = new_angles
//
// RNG: JAX threefry2x32, key = (0, 42), partitionable scheme (JAX >= 0.5 default):
//   per element i: (y0,y1) = threefry2x32((0,42), (0, i)); bits = y0 ^ y1
//   u = bitcast((bits >> 9) | 0x3f800000) - 1.0f

#define DEVINL __device__ __forceinline__

DEVINL uint32_t rotl32(uint32_t x, int d) { return __funnelshift_l(x, x, d); }

DEVINL uint32_t threefry_bits(uint32_t ctr) {
    const uint32_t ks0 = 0u;
    const uint32_t ks1 = 42u;
    const uint32_t ks2 = 0x1BD11BDAu ^ 0u ^ 42u;
    uint32_t x0 = 0u + ks0;     // hi counter = 0
    uint32_t x1 = ctr + ks1;    // lo counter = element index
#define TF_ROUND(r) { x0 += x1; x1 = rotl32(x1, (r)); x1 ^= x0; }
    TF_ROUND(13) TF_ROUND(15) TF_ROUND(26) TF_ROUND(6)
    x0 += ks1; x1 += ks2 + 1u;
    TF_ROUND(17) TF_ROUND(29) TF_ROUND(16) TF_ROUND(24)
    x0 += ks2; x1 += ks0 + 2u;
    TF_ROUND(13) TF_ROUND(15) TF_ROUND(26) TF_ROUND(6)
    x0 += ks0; x1 += ks1 + 3u;
    TF_ROUND(17) TF_ROUND(29) TF_ROUND(16) TF_ROUND(24)
    x0 += ks1; x1 += ks2 + 4u;
    TF_ROUND(13) TF_ROUND(15) TF_ROUND(26) TF_ROUND(6)
    x0 += ks2; x1 += ks0 + 5u;
#undef TF_ROUND
    return x0 ^ x1;   // 32-bit partitionable output
}

DEVINL void wmeas_elem(float x, float a, float lr, uint32_t idx,
                       float& meas_out, float& nang_out) {
    const float HALF_PI = 1.5707963267948966f;
    const float SIN_G   = 0.7071067811865476f;   // sin(pi/4)

    // uniform in [0,1) exactly as JAX constructs it
    uint32_t bits = threefry_bits(idx);
    float u = __uint_as_float((bits >> 9) | 0x3f800000u) - 1.0f;

    // thetas = (pi/2) * (last_res - tanh(input / 0.5))
    float th = HALF_PI * (lr - tanhf(x * 2.0f));
    float t  = a + th;

    float s, c;
    sincosf(0.5f * t, &s, &c);          // betas = s
    float exp_z = c * c - s * s;        // = cos(t), same formula as reference
    float ez    = exp_z * SIN_G;        // exp_z_anc

    float p0 = fmaxf((1.0f + ez) * 0.5f, 0.0f);
    float p1 = fmaxf((1.0f - ez) * 0.5f, 0.0f);
    float ratio = p0 / (p0 + p1);

    float meas = (u < ratio) ? 1.0f : -1.0f;

    float num  = 1.0f - meas * SIN_G;
    float den  = 1.0f + meas * ez;
    float side = s * sqrtf(num / den);
    side = fminf(fmaxf(side, -1.0f), 1.0f);

    meas_out = meas;
    nang_out = 2.0f * asinf(side);
}

__global__ void __launch_bounds__(256)
wmeasure_rot_kernel(const float4* __restrict__ inp,
                    const float4* __restrict__ ang,
                    const float4* __restrict__ lres,
                    float4* __restrict__ out_meas,
                    float4* __restrict__ out_ang) {
    int t = blockIdx.x * blockDim.x + threadIdx.x;
    uint32_t base = (uint32_t)t * 4u;

    float4 x = inp[t];
    float4 a = ang[t];
    float4 l = lres[t];

    float4 m, na;
    wmeas_elem(x.x, a.x, l.x, base + 0u, m.x, na.x);
    wmeas_elem(x.y, a.y, l.y, base + 1u, m.y, na.y);
    wmeas_elem(x.z, a.z, l.z, base + 2u, m.z, na.z);
    wmeas_elem(x.w, a.w, l.w, base + 3u, m.w, na.w);

    out_meas[t] = m;
    out_ang[t]  = na;
}

extern "C" void kernel_launch(void* const* d_in, const int* in_sizes, int n_in,
                              void* d_out, int out_size) {
    const float* inp  = (const float*)d_in[0];
    const float* ang  = (const float*)d_in[1];
    const float* lres = (const float*)d_in[2];
    float* out = (float*)d_out;

    int n = in_sizes[0];                 // B*N = 33554432 (divisible by 1024)
    int threads = n / 4;
    int block = 256;
    int grid = (threads + block - 1) / block;

    wmeasure_rot_kernel<<<grid, block>>>(
        (const float4*)inp, (const float4*)ang, (const float4*)lres,
        (float4*)out, (float4*)(out + n));
}

// round 2
// speedup vs baseline: 1.4397x; 1.4397x over previous
#include <cuda_runtime.h>
#include <cstdint>

// WMeasure_Rot: elementwise quantum-measurement update.
// inputs:  d_in[0]=input f32, d_in[1]=angles f32, d_in[2]=last_res f32  (each B*N)
// output:  d_out[0:B*N) = meas_res,  d_out[B*N:2*B*N) = new_angles
//
// RNG (verified bit-exact in R1): JAX threefry2x32, key=(0,42), partitionable:
//   bits(i) = x0^x1 of threefry2x32((0,42),(0,i)); u = bitcast((bits>>9)|0x3f800000)-1
//
// R2: issue/ALU-bound (183 instr/elem). Replace accurate transcendentals with
// MUFU paths within a quantified measurement-flip budget (~30 flips expected,
// rel_err ~5e-5 << 1e-3). Threefry stays exact.

#define DEVINL __device__ __forceinline__

DEVINL uint32_t rotl32(uint32_t x, int d) { return __funnelshift_l(x, x, d); }

DEVINL uint32_t threefry_bits(uint32_t ctr) {
    const uint32_t ks0 = 0u;
    const uint32_t ks1 = 42u;
    const uint32_t ks2 = 0x1BD11BDAu ^ 0u ^ 42u;
    uint32_t x0 = 0u + ks0;     // hi counter word = 0
    uint32_t x1 = ctr + ks1;    // lo counter word = element index
#define TF_ROUND(r) { x0 += x1; x1 = rotl32(x1, (r)); x1 ^= x0; }
    TF_ROUND(13) TF_ROUND(15) TF_ROUND(26) TF_ROUND(6)
    x0 += ks1; x1 += ks2 + 1u;
    TF_ROUND(17) TF_ROUND(29) TF_ROUND(16) TF_ROUND(24)
    x0 += ks2; x1 += ks0 + 2u;
    TF_ROUND(13) TF_ROUND(15) TF_ROUND(26) TF_ROUND(6)
    x0 += ks0; x1 += ks1 + 3u;
    TF_ROUND(17) TF_ROUND(29) TF_ROUND(16) TF_ROUND(24)
    x0 += ks1; x1 += ks2 + 4u;
    TF_ROUND(13) TF_ROUND(15) TF_ROUND(26) TF_ROUND(6)
    x0 += ks2; x1 += ks0 + 5u;
#undef TF_ROUND
    return x0 ^ x1;
}

// tanh(2x) = (e^{4x}-1)/(e^{4x}+1), MUFU.EX2 + MUFU.RCP. abs err ~4e-7.
DEVINL float fast_tanh2x(float x) {
    float e = __expf(fminf(4.0f * x, 80.0f));   // e^{-inf}->0 is fine; clamp top
    return __fdividef(e - 1.0f, e + 1.0f);
}

DEVINL float sqrt_approx(float x) {
    float r;
    asm("sqrt.approx.f32 %0, %1;" : "=f"(r) : "f"(x));   // MUFU.SQRT, sqrt(0)=0
    return r;
}

// 2*asin(x), x in [-1,1].  A&S 4.4.46 / DirectXMath coefficients:
// asin(a) = pi/2 - sqrt(1-a)*P7(a), |err| <= 2e-8 on [0,1].
DEVINL float two_asin(float x) {
    float a = fabsf(x);
    float t = sqrt_approx(1.0f - a);
    float p = -0.0012624911f;
    p = fmaf(p, a, 0.0066700901f);
    p = fmaf(p, a, -0.0170881256f);
    p = fmaf(p, a, 0.0308918810f);
    p = fmaf(p, a, -0.0501743046f);
    p = fmaf(p, a, 0.0889789874f);
    p = fmaf(p, a, -0.2145988016f);
    p = fmaf(p, a, 1.5707963050f);
    float m = t * p;
    float v = fmaf(-2.0f, m, 3.14159265358979323846f);   // 2*asin(|x|) = pi - 2*t*P
    return copysignf(v, x);
}

DEVINL void wmeas_elem(float x, float a, float lr, uint32_t idx,
                       float& meas_out, float& nang_out) {
    const float HALF_PI = 1.5707963267948966f;
    const float SIN_G   = 0.70710678f;   // f32(sin(pi/4)), matches reference f32 constant

    uint32_t bits = threefry_bits(idx);
    float u = __uint_as_float((bits >> 9) | 0x3f800000u) - 1.0f;

    float tnh = fast_tanh2x(x);                    // tanh(input/0.5)
    float t   = fmaf(HALF_PI, lr - tnh, a);        // angles + (pi/2)(lr - tanh)
    float ht  = 0.5f * t;

    float s = __sinf(ht);                          // betas
    float c = __cosf(ht);
    float exp_z = c * c - s * s;                   // cos(t), reference formula
    float ez = exp_z * SIN_G;                      // |ez| <= 0.7071 -> clips are no-ops

    float p0 = (1.0f + ez) * 0.5f;                 // mirror reference rounding
    float p1 = (1.0f - ez) * 0.5f;
    float ratio = __fdividef(p0, p0 + p1);

    bool plus = u < ratio;
    float meas = plus ? 1.0f : -1.0f;

    // num = 1 - meas*SIN_G (exact constants); den = 1 + meas*ez = 2*(plus?p0:p1)
    float num = plus ? (1.0f - SIN_G) : (1.0f + SIN_G);
    float den = 2.0f * (plus ? p0 : p1);

    float q  = __fdividef(num, den);               // q in [0.17, 5.83], never 0
    float sq = q * rsqrtf(q);                      // sqrt(q), MUFU.RSQ + mul
    float side = s * sq;
    side = fminf(fmaxf(side, -1.0f), 1.0f);

    meas_out = meas;
    nang_out = two_asin(side);
}

__global__ void __launch_bounds__(256)
wmeasure_rot_kernel(const float4* __restrict__ inp,
                    const float4* __restrict__ ang,
                    const float4* __restrict__ lres,
                    float4* __restrict__ out_meas,
                    float4* __restrict__ out_ang) {
    int t = blockIdx.x * blockDim.x + threadIdx.x;
    uint32_t base = (uint32_t)t * 4u;

    float4 x = inp[t];
    float4 a = ang[t];
    float4 l = lres[t];

    float4 m, na;
    wmeas_elem(x.x, a.x, l.x, base + 0u, m.x, na.x);
    wmeas_elem(x.y, a.y, l.y, base + 1u, m.y, na.y);
    wmeas_elem(x.z, a.z, l.z, base + 2u, m.z, na.z);
    wmeas_elem(x.w, a.w, l.w, base + 3u, m.w, na.w);

    out_meas[t] = m;
    out_ang[t]  = na;
}

extern "C" void kernel_launch(void* const* d_in, const int* in_sizes, int n_in,
                              void* d_out, int out_size) {
    const float* inp  = (const float*)d_in[0];
    const float* ang  = (const float*)d_in[1];
    const float* lres = (const float*)d_in[2];
    float* out = (float*)d_out;

    int n = in_sizes[0];                 // B*N = 33554432
    int threads = n / 4;
    int block = 256;
    int grid = (threads + block - 1) / block;

    wmeasure_rot_kernel<<<grid, block>>>(
        (const float4*)inp, (const float4*)ang, (const float4*)lres,
        (float4*)out, (float4*)(out + n));
}

// round 3
// speedup vs baseline: 1.5536x; 1.0791x over previous
#include <cuda_runtime.h>
#include <cstdint>

// WMeasure_Rot: elementwise quantum-measurement update.
// inputs:  d_in[0]=input f32, d_in[1]=angles f32, d_in[2]=last_res f32  (each B*N)
// output:  d_out[0:B*N) = meas_res,  d_out[B*N:2*B*N) = new_angles
//
// RNG (bit-exact, verified R1): JAX threefry2x32, key=(0,42), partitionable.
// R3: trim FMA-pipe float work so ptxas can migrate threefry IMADs off the
// saturated ALU pipe. All approximation deltas quantified against the
// measurement-flip budget (~9 expected flips, rel_err ~6e-4 < 1e-3).

#define DEVINL __device__ __forceinline__

DEVINL uint32_t rotl32(uint32_t x, int d) { return __funnelshift_l(x, x, d); }

DEVINL uint32_t threefry_bits(uint32_t ctr) {
    const uint32_t ks0 = 0u;
    const uint32_t ks1 = 42u;
    const uint32_t ks2 = 0x1BD11BDAu ^ 0u ^ 42u;
    uint32_t x0 = 0u + ks0;     // hi counter word = 0
    uint32_t x1 = ctr + ks1;    // lo counter word = element index
#define TF_ROUND(r) { x0 += x1; x1 = rotl32(x1, (r)); x1 ^= x0; }
    TF_ROUND(13) TF_ROUND(15) TF_ROUND(26) TF_ROUND(6)
    x0 += ks1; x1 += ks2 + 1u;
    TF_ROUND(17) TF_ROUND(29) TF_ROUND(16) TF_ROUND(24)
    x0 += ks2; x1 += ks0 + 2u;
    TF_ROUND(13) TF_ROUND(15) TF_ROUND(26) TF_ROUND(6)
    x0 += ks0; x1 += ks1 + 3u;
    TF_ROUND(17) TF_ROUND(29) TF_ROUND(16) TF_ROUND(24)
    x0 += ks1; x1 += ks2 + 4u;
    TF_ROUND(13) TF_ROUND(15) TF_ROUND(26) TF_ROUND(6)
    x0 += ks2; x1 += ks0 + 5u;
#undef TF_ROUND
    return x0 ^ x1;
}

DEVINL float mufu_ex2(float x)  { float r; asm("ex2.approx.f32 %0, %1;"  : "=f"(r) : "f"(x)); return r; }
DEVINL float mufu_rcp(float x)  { float r; asm("rcp.approx.f32 %0, %1;"  : "=f"(r) : "f"(x)); return r; }
DEVINL float mufu_rsq(float x)  { float r; asm("rsqrt.approx.f32 %0, %1;": "=f"(r) : "f"(x)); return r; }
DEVINL float mufu_sqrt(float x) { float r; asm("sqrt.approx.f32 %0, %1;" : "=f"(r) : "f"(x)); return r; }
DEVINL float mufu_sin(float x)  { float r; asm("sin.approx.f32 %0, %1;"  : "=f"(r) : "f"(x)); return r; }

DEVINL void wmeas_elem(float x, float a, float lr, uint32_t idx,
                       float& meas_out, float& nang_out) {
    const float HALF_PI    = 1.5707963267948966f;
    const float SIN_G      = 0.70710678f;           // f32(sin(pi/4))
    const float FOURLOG2E  = 5.770780163555852f;    // 4/ln(2)
    const float K_PLUS     = 0.3826834323650898f;   // sqrt((1-SIN_G)/2)
    const float K_MINUS    = 0.9238795325112867f;   // sqrt((1+SIN_G)/2)

    // u in [0,1), exactly as JAX constructs it
    uint32_t bits = threefry_bits(idx);
    float u = __uint_as_float((bits >> 9) | 0x3f800000u) - 1.0f;

    // tanh(2x) = 1 - 2/(e^{4x}+1); ex2->inf->rcp->0 saturates exactly, no clamp
    float e   = mufu_ex2(x * FOURLOG2E);
    float tnh = fmaf(-2.0f, mufu_rcp(e + 1.0f), 1.0f);

    float t  = fmaf(HALF_PI, lr - tnh, a);   // temp_angles
    float s  = mufu_sin(0.5f * t);           // betas
    float exp_z = fmaf(-2.0f * s, s, 1.0f);  // cos(t) = 1 - 2 sin^2(t/2)
    float ez = exp_z * SIN_G;                // |ez| <= 0.7071 -> no clipping ever

    float p0 = (1.0f + ez) * 0.5f;           // bit-identical to reference p0
    float p1 = (1.0f - ez) * 0.5f;

    // reference: u < p0/(p0+p1); p0+p1 = 1 +- 2^-24 -> boundary shift <= 1e-7
    bool plus = u < p0;
    float meas = plus ? 1.0f : -1.0f;

    // side = betas * sqrt((1-meas*SIN_G)/(1+meas*ez)) = s * K(+/-) * rsqrt(p(+/-))
    float K = plus ? K_PLUS : K_MINUS;
    float p = plus ? p0 : p1;
    float side = s * K * mufu_rsq(p);
    side = fminf(fmaxf(side, -1.0f), 1.0f);

    // 2*asin(side): A&S 4.4.45 degree-3, |eps| <= 6.8e-5
    float aa = fabsf(side);
    float sq = mufu_sqrt(1.0f - aa);
    float poly = -0.0187293f;
    poly = fmaf(poly, aa, 0.0742610f);
    poly = fmaf(poly, aa, -0.2121144f);
    poly = fmaf(poly, aa, 1.5707288f);
    float v = fmaf(-2.0f, sq * poly, 3.14159265358979f); // 2*asin(|side|)

    meas_out = meas;
    nang_out = copysignf(v, side);
}

__global__ void __launch_bounds__(256)
wmeasure_rot_kernel(const float4* __restrict__ inp,
                    const float4* __restrict__ ang,
                    const float4* __restrict__ lres,
                    float4* __restrict__ out_meas,
                    float4* __restrict__ out_ang) {
    int t = blockIdx.x * blockDim.x + threadIdx.x;
    uint32_t base = (uint32_t)t * 4u;

    float4 x = inp[t];
    float4 a = ang[t];
    float4 l = lres[t];

    float4 m, na;
    wmeas_elem(x.x, a.x, l.x, base + 0u, m.x, na.x);
    wmeas_elem(x.y, a.y, l.y, base + 1u, m.y, na.y);
    wmeas_elem(x.z, a.z, l.z, base + 2u, m.z, na.z);
    wmeas_elem(x.w, a.w, l.w, base + 3u, m.w, na.w);

    out_meas[t] = m;
    out_ang[t]  = na;
}

extern "C" void kernel_launch(void* const* d_in, const int* in_sizes, int n_in,
                              void* d_out, int out_size) {
    const float* inp  = (const float*)d_in[0];
    const float* ang  = (const float*)d_in[1];
    const float* lres = (const float*)d_in[2];
    float* out = (float*)d_out;

    int n = in_sizes[0];                 // B*N = 33554432
    int threads = n / 4;
    int block = 256;
    int grid = (threads + block - 1) / block;

    wmeasure_rot_kernel<<<grid, block>>>(
        (const float4*)inp, (const float4*)ang, (const float4*)lres,
        (float4*)out, (float4*)(out + n));
}

// round 5
// speedup vs baseline: 1.6082x; 1.0351x over previous
#include <cuda_runtime.h>
#include <cstdint>

// WMeasure_Rot: elementwise quantum-measurement update.
// inputs:  d_in[0]=input f32, d_in[1]=angles f32, d_in[2]=last_res f32  (each B*N)
// output:  d_out[0:B*N) = meas_res,  d_out[B*N:2*B*N) = new_angles
//
// RNG (bit-exact, verified R1): JAX threefry2x32, key=(0,42), partitionable.
// R5 = R4 with corrected K_HDF constant (R4 had a transposed digit:
// 0.27069805 instead of 0.27059805, which systematically skewed `side` by
// ~2.6e-4 rel and blew up new_angles via the asin derivative near |side|=1).
// Structure: f in [1,2) compared directly against 1.5+ez/2 (u=f-1 Sterbenz-
// exact); K and p reconstructed by FMA on meas (no SELs); fused ez; doubled
// asin poly. Flip budget ~1-5 -> out0 ~3.5e-4, out1 ~5e-4.

#define DEVINL __device__ __forceinline__

DEVINL uint32_t rotl32(uint32_t x, int d) { return __funnelshift_l(x, x, d); }

DEVINL uint32_t threefry_bits(uint32_t ctr) {
    const uint32_t ks0 = 0u;
    const uint32_t ks1 = 42u;
    const uint32_t ks2 = 0x1BD11BDAu ^ 0u ^ 42u;
    uint32_t x0 = 0u + ks0;     // hi counter word = 0
    uint32_t x1 = ctr + ks1;    // lo counter word = element index
#define TF_ROUND(r) { x0 += x1; x1 = rotl32(x1, (r)); x1 ^= x0; }
    TF_ROUND(13) TF_ROUND(15) TF_ROUND(26) TF_ROUND(6)
    x0 += ks1; x1 += ks2 + 1u;
    TF_ROUND(17) TF_ROUND(29) TF_ROUND(16) TF_ROUND(24)
    x0 += ks2; x1 += ks0 + 2u;
    TF_ROUND(13) TF_ROUND(15) TF_ROUND(26) TF_ROUND(6)
    x0 += ks0; x1 += ks1 + 3u;
    TF_ROUND(17) TF_ROUND(29) TF_ROUND(16) TF_ROUND(24)
    x0 += ks1; x1 += ks2 + 4u;
    TF_ROUND(13) TF_ROUND(15) TF_ROUND(26) TF_ROUND(6)
    x0 += ks2; x1 += ks0 + 5u;
#undef TF_ROUND
    return x0 ^ x1;
}

DEVINL float mufu_ex2(float x)  { float r; asm("ex2.approx.f32 %0, %1;"  : "=f"(r) : "f"(x)); return r; }
DEVINL float mufu_rcp(float x)  { float r; asm("rcp.approx.f32 %0, %1;"  : "=f"(r) : "f"(x)); return r; }
DEVINL float mufu_rsq(float x)  { float r; asm("rsqrt.approx.f32 %0, %1;": "=f"(r) : "f"(x)); return r; }
DEVINL float mufu_sqrt(float x) { float r; asm("sqrt.approx.f32 %0, %1;" : "=f"(r) : "f"(x)); return r; }
DEVINL float mufu_sin(float x)  { float r; asm("sin.approx.f32 %0, %1;"  : "=f"(r) : "f"(x)); return r; }

DEVINL void wmeas_elem(float x, float a, float lr, uint32_t idx,
                       float& meas_out, float& nang_out) {
    const float PI_4       = 0.7853981633974483f;   // pi/4
    const float PI_2       = 1.5707963267948966f;   // pi/2
    const float SIN_G      = 0.70710678f;           // f32(sin(pi/4))
    const float FOURLOG2E  = 5.770780163555852f;    // 4/ln(2)
    const float K_MID      = 0.6532814824381883f;   // (K_PLUS+K_MINUS)/2
    const float K_HDF      = 0.2705980500730985f;   // (K_MINUS-K_PLUS)/2  [FIXED]

    // f in [1,2): u = f - 1 exactly (Sterbenz)
    uint32_t bits = threefry_bits(idx);
    float f = __uint_as_float((bits >> 9) | 0x3f800000u);

    // tanh(2x) = 1 - 2*rcp(e^{4x}+1); ex2->inf->rcp->0 saturates exactly.
    // ht = 0.5*angles + (pi/4)*(lr - tanh) = [0.5a + (pi/4)(lr-1)] + (pi/2)*r
    float e  = mufu_ex2(x * FOURLOG2E);
    float r  = mufu_rcp(e + 1.0f);
    float base = fmaf(PI_4, lr - 1.0f, 0.5f * a);   // lr-1 in {0,-2}: exact
    float ht = fmaf(PI_2, r, base);

    float s  = mufu_sin(ht);                        // betas
    float ez = fmaf(-2.0f * SIN_G * s, s, SIN_G);   // sin(g)*cos(t), |ez|<=0.7071
    float hez = 0.5f * ez;                          // exact scaling

    // reference: u < p0/(p0+p1) ~ (1+ez)/2; here: f < 1.5 + ez/2 (shift ~1e-7)
    float meas = (f < hez + 1.5f) ? 1.0f : -1.0f;

    // side = s * sqrt((1 - meas*SIN_G)/(1 + meas*ez)) = s * K(meas) * rsqrt(p)
    float p = fmaf(meas, hez, 0.5f);                // (1 + meas*ez)/2 in [0.146,0.854]
    float K = fmaf(meas, -K_HDF, K_MID);            // K_PLUS / K_MINUS to 1 ulp
    float side = (s * K) * mufu_rsq(p);

    // 2*asin(side): A&S 4.4.45 deg-3, coefficients pre-doubled
    float aa = fminf(fabsf(side), 1.0f);            // single clamp
    float sq = mufu_sqrt(1.0f - aa);
    float poly = -0.0374586f;                       // 2 * coeffs
    poly = fmaf(poly, aa, 0.1485220f);
    poly = fmaf(poly, aa, -0.4242288f);
    poly = fmaf(poly, aa, 3.1414576f);
    float v = fmaf(-sq, poly, 3.14159265358979f);   // 2*asin(|side|)

    meas_out = meas;
    nang_out = copysignf(v, side);
}

__global__ void __launch_bounds__(256)
wmeasure_rot_kernel(const float4* __restrict__ inp,
                    const float4* __restrict__ ang,
                    const float4* __restrict__ lres,
                    float4* __restrict__ out_meas,
                    float4* __restrict__ out_ang) {
    int t = blockIdx.x * blockDim.x + threadIdx.x;
    uint32_t base = (uint32_t)t * 4u;

    float4 x = inp[t];
    float4 a = ang[t];
    float4 l = lres[t];

    float4 m, na;
    wmeas_elem(x.x, a.x, l.x, base + 0u, m.x, na.x);
    wmeas_elem(x.y, a.y, l.y, base + 1u, m.y, na.y);
    wmeas_elem(x.z, a.z, l.z, base + 2u, m.z, na.z);
    wmeas_elem(x.w, a.w, l.w, base + 3u, m.w, na.w);

    out_meas[t] = m;
    out_ang[t]  = na;
}

extern "C" void kernel_launch(void* const* d_in, const int* in_sizes, int n_in,
                              void* d_out, int out_size) {
    const float* inp  = (const float*)d_in[0];
    const float* ang  = (const float*)d_in[1];
    const float* lres = (const float*)d_in[2];
    float* out = (float*)d_out;

    int n = in_sizes[0];                 // B*N = 33554432
    int threads = n / 4;
    int block = 256;
    int grid = (threads + block - 1) / block;

    wmeasure_rot_kernel<<<grid, block>>>(
        (const float4*)inp, (const float4*)ang, (const float4*)lres,
        (float4*)out, (float4*)(out + n));
}

// round 6
// speedup vs baseline: 1.6332x; 1.0156x over previous
#include <cuda_runtime.h>
#include <cstdint>

// WMeasure_Rot: elementwise quantum-measurement update.
// inputs:  d_in[0]=input f32, d_in[1]=angles f32, d_in[2]=last_res f32  (each B*N)
// output:  d_out[0:B*N) = meas_res,  d_out[B*N:2*B*N) = new_angles
//
// RNG (bit-exact, verified R1): JAX threefry2x32, key=(0,42), partitionable.
// R6 = R5 math (unchanged, 1 flip, rel_err 3.45e-4) at 8 elements/thread.
// Rationale: ALU-pipe rt is the measured binder (48 ops/elem -> ~90us floor);
// the 121 vs 90us gap is threefry's serial IADD->SHF->LOP3 dependency chain.
// 8 independent chains/thread cover the ALU issue slots; threefry needs no
// loaded data, so LDG latency hides behind RNG compute even at low occupancy.

#define DEVINL __device__ __forceinline__

DEVINL uint32_t rotl32(uint32_t x, int d) { return __funnelshift_l(x, x, d); }

DEVINL uint32_t threefry_bits(uint32_t ctr) {
    const uint32_t ks0 = 0u;
    const uint32_t ks1 = 42u;
    const uint32_t ks2 = 0x1BD11BDAu ^ 0u ^ 42u;
    uint32_t x0 = 0u + ks0;     // hi counter word = 0
    uint32_t x1 = ctr + ks1;    // lo counter word = element index
#define TF_ROUND(r) { x0 += x1; x1 = rotl32(x1, (r)); x1 ^= x0; }
    TF_ROUND(13) TF_ROUND(15) TF_ROUND(26) TF_ROUND(6)
    x0 += ks1; x1 += ks2 + 1u;
    TF_ROUND(17) TF_ROUND(29) TF_ROUND(16) TF_ROUND(24)
    x0 += ks2; x1 += ks0 + 2u;
    TF_ROUND(13) TF_ROUND(15) TF_ROUND(26) TF_ROUND(6)
    x0 += ks0; x1 += ks1 + 3u;
    TF_ROUND(17) TF_ROUND(29) TF_ROUND(16) TF_ROUND(24)
    x0 += ks1; x1 += ks2 + 4u;
    TF_ROUND(13) TF_ROUND(15) TF_ROUND(26) TF_ROUND(6)
    x0 += ks2; x1 += ks0 + 5u;
#undef TF_ROUND
    return x0 ^ x1;
}

DEVINL float mufu_ex2(float x)  { float r; asm("ex2.approx.f32 %0, %1;"  : "=f"(r) : "f"(x)); return r; }
DEVINL float mufu_rcp(float x)  { float r; asm("rcp.approx.f32 %0, %1;"  : "=f"(r) : "f"(x)); return r; }
DEVINL float mufu_rsq(float x)  { float r; asm("rsqrt.approx.f32 %0, %1;": "=f"(r) : "f"(x)); return r; }
DEVINL float mufu_sqrt(float x) { float r; asm("sqrt.approx.f32 %0, %1;" : "=f"(r) : "f"(x)); return r; }
DEVINL float mufu_sin(float x)  { float r; asm("sin.approx.f32 %0, %1;"  : "=f"(r) : "f"(x)); return r; }

DEVINL void wmeas_elem(float x, float a, float lr, uint32_t idx,
                       float& meas_out, float& nang_out) {
    const float PI_4       = 0.7853981633974483f;   // pi/4
    const float PI_2       = 1.5707963267948966f;   // pi/2
    const float SIN_G      = 0.70710678f;           // f32(sin(pi/4))
    const float FOURLOG2E  = 5.770780163555852f;    // 4/ln(2)
    const float K_MID      = 0.6532814824381883f;   // (K_PLUS+K_MINUS)/2
    const float K_HDF      = 0.2705980500730985f;   // (K_MINUS-K_PLUS)/2

    // f in [1,2): u = f - 1 exactly (Sterbenz)
    uint32_t bits = threefry_bits(idx);
    float f = __uint_as_float((bits >> 9) | 0x3f800000u);

    // tanh(2x) = 1 - 2*rcp(e^{4x}+1); ex2->inf->rcp->0 saturates exactly.
    float e  = mufu_ex2(x * FOURLOG2E);
    float r  = mufu_rcp(e + 1.0f);
    float base = fmaf(PI_4, lr - 1.0f, 0.5f * a);   // lr-1 in {0,-2}: exact
    float ht = fmaf(PI_2, r, base);

    float s  = mufu_sin(ht);                        // betas
    float ez = fmaf(-2.0f * SIN_G * s, s, SIN_G);   // sin(g)*cos(t), |ez|<=0.7071
    float hez = 0.5f * ez;

    // reference: u < p0/(p0+p1) ~ (1+ez)/2; here: f < 1.5 + ez/2
    float meas = (f < hez + 1.5f) ? 1.0f : -1.0f;

    // side = s * K(meas) * rsqrt(p)
    float p = fmaf(meas, hez, 0.5f);                // in [0.146, 0.854]
    float K = fmaf(meas, -K_HDF, K_MID);
    float side = (s * K) * mufu_rsq(p);

    // 2*asin(side): A&S 4.4.45 deg-3, coefficients pre-doubled
    float aa = fminf(fabsf(side), 1.0f);
    float sq = mufu_sqrt(1.0f - aa);
    float poly = -0.0374586f;
    poly = fmaf(poly, aa, 0.1485220f);
    poly = fmaf(poly, aa, -0.4242288f);
    poly = fmaf(poly, aa, 3.1414576f);
    float v = fmaf(-sq, poly, 3.14159265358979f);   // 2*asin(|side|)

    meas_out = meas;
    nang_out = copysignf(v, side);
}

__global__ void __launch_bounds__(256)
wmeasure_rot_kernel(const float4* __restrict__ inp,
                    const float4* __restrict__ ang,
                    const float4* __restrict__ lres,
                    float4* __restrict__ out_meas,
                    float4* __restrict__ out_ang) {
    int t = blockIdx.x * blockDim.x + threadIdx.x;
    int s0 = 2 * t;              // two consecutive float4 slots per thread
    int s1 = 2 * t + 1;
    uint32_t base = (uint32_t)t * 8u;

    float4 x0 = inp[s0],  x1 = inp[s1];
    float4 a0 = ang[s0],  a1 = ang[s1];
    float4 l0 = lres[s0], l1 = lres[s1];

    float xs[8] = {x0.x, x0.y, x0.z, x0.w, x1.x, x1.y, x1.z, x1.w};
    float as[8] = {a0.x, a0.y, a0.z, a0.w, a1.x, a1.y, a1.z, a1.w};
    float ls[8] = {l0.x, l0.y, l0.z, l0.w, l1.x, l1.y, l1.z, l1.w};

    float ms[8], ns[8];
#pragma unroll
    for (int j = 0; j < 8; j++)
        wmeas_elem(xs[j], as[j], ls[j], base + (uint32_t)j, ms[j], ns[j]);

    out_meas[s0] = make_float4(ms[0], ms[1], ms[2], ms[3]);
    out_meas[s1] = make_float4(ms[4], ms[5], ms[6], ms[7]);
    out_ang[s0]  = make_float4(ns[0], ns[1], ns[2], ns[3]);
    out_ang[s1]  = make_float4(ns[4], ns[5], ns[6], ns[7]);
}

extern "C" void kernel_launch(void* const* d_in, const int* in_sizes, int n_in,
                              void* d_out, int out_size) {
    const float* inp  = (const float*)d_in[0];
    const float* ang  = (const float*)d_in[1];
    const float* lres = (const float*)d_in[2];
    float* out = (float*)d_out;

    int n = in_sizes[0];                 // B*N = 33554432 (divisible by 2048)
    int threads = n / 8;
    int block = 256;
    int grid = (threads + block - 1) / block;

    wmeasure_rot_kernel<<<grid, block>>>(
        (const float4*)inp, (const float4*)ang, (const float4*)lres,
        (float4*)out, (float4*)(out + n));
}